// round 16
// baseline (speedup 1.0000x reference)
#include <cuda_runtime.h>
#include <cuda_bf16.h>
#include <cstdint>

// Problem constants
#define BB    4096
#define DD    128
#define HIST  50
#define TOPN  4
#define PROTO 1024
#define ITEMS 100000
#define KTOT  1152      // 384 text + 768 visual
#define K1    256       // MLP layer1 input
#define D2    64        // MLP layer2 output

typedef unsigned long long ull;

// ---------------- scratch (__device__ globals; no allocation allowed) ----------------
__device__ float  g_cb[DD];             // bt·Wt_row + bv·Wv_row
__device__ uint4  g_maskh4[BB*PROTO/8]; // bf16 0/1 presence mask (8MB)
__device__ __align__(16) __nv_bfloat16 g_PB2[2*128*1024];  // bf16 split protos^T [split][c][k]
__device__ __align__(16) __nv_bfloat16 g_WB2[2*128*KTOT];  // bf16 split [Wt|Wv]  [split][c][k]
__device__ __align__(16) __nv_bfloat16 g_W1B2[2*128*K1];   // bf16 split W1       [split][c][k]
__device__ __align__(16) __nv_bfloat16 g_IFB[2*BB*K1];     // bf16 split inter_feat
__device__ float  g_cinv[BB];           // 1/unique-count
__device__ float  g_s1[DD], g_q1[DD];
__device__ float  g_s2[D2], g_q2[D2];
__device__ int    g_bar1, g_bar2;       // grid-barrier counters (reset each call)

__device__ __forceinline__ void cpa16(void* dst, const void* src) {
    unsigned d = (unsigned)__cvta_generic_to_shared(dst);
    asm volatile("cp.async.cg.shared.global [%0], [%1], 16;" :: "r"(d), "l"(src));
}
__device__ __forceinline__ void cpa_commit() { asm volatile("cp.async.commit_group;"); }
__device__ __forceinline__ void cpa_wait1() { asm volatile("cp.async.wait_group 1;"); }
__device__ __forceinline__ void cpa_wait0() { asm volatile("cp.async.wait_group 0;"); }

// HMMA bf16: D(f32) += A(bf16 m16k16 row) * B(bf16 k16n8 col)
__device__ __forceinline__ void mma_bf16(float* d, uint32_t a0, uint32_t a1,
                                         uint32_t a2, uint32_t a3,
                                         uint32_t b0, uint32_t b1) {
    asm volatile("mma.sync.aligned.m16n8k16.row.col.f32.bf16.bf16.f32 "
                 "{%0,%1,%2,%3},{%4,%5,%6,%7},{%8,%9},{%0,%1,%2,%3};"
                 : "+f"(d[0]), "+f"(d[1]), "+f"(d[2]), "+f"(d[3])
                 : "r"(a0), "r"(a1), "r"(a2), "r"(a3), "r"(b0), "r"(b1));
}
__device__ __forceinline__ uint32_t pk_bf2(float lo, float hi) {
    uint32_t r;
    asm("cvt.rn.bf16x2.f32 %0, %1, %2;" : "=r"(r) : "f"(hi), "f"(lo));
    return r;
}
__device__ __forceinline__ void split2(float v0, float v1, uint32_t &hi, uint32_t &lo) {
    __nv_bfloat16 h0 = __float2bfloat16(v0), h1 = __float2bfloat16(v1);
    uint16_t u0, u1; memcpy(&u0, &h0, 2); memcpy(&u1, &h1, 2);
    hi = (uint32_t)u0 | ((uint32_t)u1 << 16);
    lo = pk_bf2(v0 - __bfloat162float(h0), v1 - __bfloat162float(h1));
}

// grid barrier: all CTAs co-resident (grid=128 <= 148 SMs, 1 CTA/SM)
__device__ __forceinline__ void gsync(int* bar, int target) {
    __syncthreads();
    if (threadIdx.x == 0) {
        __threadfence();
        atomicAdd(bar, 1);
        while (atomicAdd(bar, 0) < target) { }
        __threadfence();
    }
    __syncthreads();
}

// ---------------- prep body (runs as tail blocks of k_xp, 128 threads) --------------
__device__ void prep_body(int blk, int tid,
                          const float* __restrict__ Wt, const float* __restrict__ Wv,
                          const float* __restrict__ W1,
                          const float* __restrict__ protos,
                          const float* __restrict__ bt, const float* __restrict__ bv) {
    if (blk >= 296) {   // cb part: 32 blocks x 4 warps = 128 columns
        int c = (blk - 296)*4 + (tid >> 5);
        int l = tid & 31;
        float s = 0.f;
        for (int k = l; k < 384; k += 32) s += bt[k] * Wt[c*384 + k];
        for (int k = l; k < 768; k += 32) s += bv[k] * Wv[c*768 + k];
        #pragma unroll
        for (int o = 16; o; o >>= 1) s += __shfl_down_sync(0xffffffffu, s, o);
        if (l == 0) g_cb[c] = s;
        return;
    }
    const int n_wb = 128*KTOT;
    const int n_pb = 128*1024;
    const int n_w1 = 128*K1;
    const int n_z  = 2*DD + 2*D2 + 2;
    int total = n_wb + n_pb + n_w1 + n_z;
    for (int i = blk*128 + tid; i < total; i += 296*128) {
        if (i < n_wb) {
            int c = i / KTOT, k = i % KTOT;
            float v = (k < 384) ? Wt[c*384 + k] : Wv[c*768 + (k - 384)];
            __nv_bfloat16 b1 = __float2bfloat16(v);
            g_WB2[i]            = b1;
            g_WB2[128*KTOT + i] = __float2bfloat16(v - __bfloat162float(b1));
        } else if (i < n_wb + n_pb) {
            int j = i - n_wb; int c = j & 127; int k = j >> 7;
            float p = protos[k*DD + c];
            __nv_bfloat16 b1 = __float2bfloat16(p);
            g_PB2[c*1024 + k]          = b1;
            g_PB2[131072 + c*1024 + k] = __float2bfloat16(p - __bfloat162float(b1));
        } else if (i < n_wb + n_pb + n_w1) {
            int j = i - n_wb - n_pb;
            float v = W1[j];
            __nv_bfloat16 b1 = __float2bfloat16(v);
            g_W1B2[j]          = b1;
            g_W1B2[128*K1 + j] = __float2bfloat16(v - __bfloat162float(b1));
        } else {
            int j = i - n_wb - n_pb - n_w1;
            if (j < DD)               g_s1[j] = 0.f;
            else if (j < 2*DD)        g_q1[j-DD] = 0.f;
            else if (j < 2*DD+D2)     g_s2[j-2*DD] = 0.f;
            else if (j < 2*DD+2*D2)   g_q2[j-2*DD-D2] = 0.f;
            else if (j == 2*DD+2*D2)  g_bar1 = 0;
            else                      g_bar2 = 0;
        }
    }
}

// ---------------- fused: mask build + prompt gathers + prep -------------------------
__global__ void __launch_bounds__(128) k_xp(
        const int* __restrict__ nodes_u, const int* __restrict__ nodes_v,
        const int* __restrict__ nodes_d, const int* __restrict__ inter_items,
        const int* __restrict__ top_n,
        const float* __restrict__ up, const float* __restrict__ dp,
        float* __restrict__ out_pu, float* __restrict__ out_pd,
        const float* __restrict__ Wt, const float* __restrict__ Wv,
        const float* __restrict__ W1,
        const float* __restrict__ protos,
        const float* __restrict__ bt, const float* __restrict__ bv) {
    __shared__ unsigned bm[PROTO/32];
    int tid = threadIdx.x;
    if (blockIdx.x >= BB) {
        prep_body(blockIdx.x - BB, tid, Wt, Wv, W1, protos, bt, bv);
        return;
    }
    int s = blockIdx.x;
    if (tid < 32) bm[tid] = 0u;
    __syncthreads();
    if (tid < HIST) {
        int item = inter_items[s*HIST + tid];
        int4 r1 = ((const int4*)top_n)[item];
        int4 r2 = ((const int4*)top_n)[item + ITEMS];
        atomicOr(&bm[r1.x >> 5], 1u << (r1.x & 31));
        atomicOr(&bm[r1.y >> 5], 1u << (r1.y & 31));
        atomicOr(&bm[r1.z >> 5], 1u << (r1.z & 31));
        atomicOr(&bm[r1.w >> 5], 1u << (r1.w & 31));
        atomicOr(&bm[r2.x >> 5], 1u << (r2.x & 31));
        atomicOr(&bm[r2.y >> 5], 1u << (r2.y & 31));
        atomicOr(&bm[r2.z >> 5], 1u << (r2.z & 31));
        atomicOr(&bm[r2.w >> 5], 1u << (r2.w & 31));
    }
    __syncthreads();
    if (tid < 32) {
        unsigned c = __popc(bm[tid]);
        #pragma unroll
        for (int o = 16; o; o >>= 1) c += __shfl_down_sync(0xffffffffu, c, o);
        if (tid == 0) g_cinv[s] = 1.0f / (float)c;
    }
    unsigned w = bm[tid >> 2];
    int sh = (tid & 3) * 8;
    uint32_t pk[4];
    #pragma unroll
    for (int q = 0; q < 4; ++q) {
        uint32_t lo = ((w >> (sh + 2*q)) & 1) ? 0x3F80u : 0u;
        uint32_t hi = ((w >> (sh + 2*q + 1)) & 1) ? 0x3F80u : 0u;
        pk[q] = lo | (hi << 16);
    }
    g_maskh4[(size_t)s*128 + tid] = make_uint4(pk[0], pk[1], pk[2], pk[3]);
    out_pu[s*DD + tid] = up[nodes_u[s]*DD + tid];
    out_pd[s*DD + tid] = dp[nodes_d[s]*DD + tid];
}

// ===================================================================================
// HMMA GEMM: M=32 x N=128, BK=64, depth-2 pipeline.
// e buffer: [Af32 32x272][Ahi 32x144][Alo 32x144][Bhi 128x144][Blo 128x144] = 54784
// hu buffer: [A 32x144][pad][Bhi][Blo] = 46080 (uses its own stride)
// ===================================================================================
#define BK     64
#define TA_SZ  (32*144)
#define TB_SZ  (128*144)
#define AF_SZ  (32*272)
#define AH_OFF AF_SZ                    // 8704
#define AL_OFF (AF_SZ + TA_SZ)          // 13312
#define EB_OFF (AF_SZ + 2*TA_SZ)        // 17920
#define E_BUF  (EB_OFF + 2*TB_SZ)       // 54784
#define HU_BUF (2*TA_SZ + 2*TB_SZ)      // 46080
#define EH_SMEM (2*E_BUF)               // 109568

#define MMA_DECL                                                                \
    int tid = threadIdx.x;                                                      \
    int w = tid >> 5, lane = tid & 31;                                          \
    int gr = lane >> 2, kb = (lane & 3) * 2;                                    \
    float d[2][2][4];                                                           \
    _Pragma("unroll")                                                           \
    for (int mi = 0; mi < 2; ++mi)                                              \
        _Pragma("unroll")                                                       \
        for (int ni = 0; ni < 2; ++ni)                                          \
            _Pragma("unroll")                                                   \
            for (int q = 0; q < 4; ++q) d[mi][ni][q] = 0.f;

#define LOAD_A(dst, SRC, r0, k)                                                 \
    dst[0] = *(const uint32_t*)&SRC[(r0)*72 + (k)];                             \
    dst[1] = *(const uint32_t*)&SRC[((r0)+8)*72 + (k)];                         \
    dst[2] = *(const uint32_t*)&SRC[(r0)*72 + (k) + 8];                         \
    dst[3] = *(const uint32_t*)&SRC[((r0)+8)*72 + (k) + 8];

// ---------------- e body: direct fp32 gather + in-smem split, 3 term-groups --------
__device__ __forceinline__ void e_body(char* sm, int blk,
                                       const int* __restrict__ nodes_v,
                                       const float* __restrict__ pre_text,
                                       const float* __restrict__ pre_visual,
                                       const float* __restrict__ ip) {
    __shared__ int svs[32];
    MMA_DECL;
    if (tid < 32) svs[tid] = nodes_v[blk*32 + tid];
    __syncthreads();

    auto stage = [&](int ch, int b) {
        char* base = sm + b*E_BUF;
        int kk = ch * BK;                  // float offset within row
        // A fp32: 32 rows x 256B, 2 transfers/thread
        #pragma unroll
        for (int i = 0; i < 2; ++i) {
            int idx = tid + i*256; int r = idx >> 4, pc = idx & 15;
            int row = svs[r];
            const char* src = (kk < 384)
                ? (const char*)(pre_text + (size_t)row*384 + kk) + pc*16
                : (const char*)(pre_visual + (size_t)row*768 + (kk - 384)) + pc*16;
            cpa16(base + r*272 + pc*16, src);
        }
        // B tiles: both weight splits
        #pragma unroll
        for (int sb = 0; sb < 2; ++sb) {
            char* Bd = base + EB_OFF + sb*TB_SZ;
            const char* bbase = (const char*)g_WB2 + (size_t)sb*128*KTOT*2;
            #pragma unroll
            for (int i = 0; i < 4; ++i) {
                int idx = tid + i*256; int c = idx >> 3, pc = idx & 7;
                cpa16(Bd + c*144 + pc*16, bbase + (size_t)c*(KTOT*2) + kk*2 + pc*16);
            }
        }
        cpa_commit();
    };

    const int NCH = KTOT/BK;   // 18
    stage(0, 0);
    #pragma unroll 1
    for (int ch = 0; ch < NCH; ++ch) {
        __syncthreads();
        if (ch + 1 < NCH) { stage(ch + 1, (ch + 1) & 1); cpa_wait1(); }
        else cpa_wait0();
        __syncthreads();
        char* base = sm + (ch & 1)*E_BUF;
        // convert fp32 chunk -> bf16 hi/lo tiles (each thread: 8 floats of one row)
        {
            const float* Af = (const float*)base;
            __nv_bfloat16* Ah = (__nv_bfloat16*)(base + AH_OFF);
            __nv_bfloat16* Al = (__nv_bfloat16*)(base + AL_OFF);
            int r = tid >> 3, j = tid & 7;
            const float* p = Af + r*68 + j*8;
            uint32_t hh[4], ll[4];
            #pragma unroll
            for (int q = 0; q < 4; ++q) split2(p[2*q], p[2*q+1], hh[q], ll[q]);
            *(uint4*)&Ah[r*72 + j*8] = make_uint4(hh[0], hh[1], hh[2], hh[3]);
            *(uint4*)&Al[r*72 + j*8] = make_uint4(ll[0], ll[1], ll[2], ll[3]);
        }
        __syncthreads();
        const __nv_bfloat16* A1 = (const __nv_bfloat16*)(base + AH_OFF);
        const __nv_bfloat16* A2 = (const __nv_bfloat16*)(base + AL_OFF);
        const __nv_bfloat16* B1 = (const __nv_bfloat16*)(base + EB_OFF);
        const __nv_bfloat16* B2 = (const __nv_bfloat16*)(base + EB_OFF + TB_SZ);
        #pragma unroll
        for (int ks = 0; ks < BK/16; ++ks) {
            int k = ks*16 + kb;
            uint32_t a1[2][4], a2[2][4];
            #pragma unroll
            for (int mi = 0; mi < 2; ++mi) {
                int r0 = mi*16 + gr;
                LOAD_A(a1[mi], A1, r0, k);
                LOAD_A(a2[mi], A2, r0, k);
            }
            #pragma unroll
            for (int ni = 0; ni < 2; ++ni) {
                int n = w*16 + ni*8 + gr;
                uint32_t b10 = *(const uint32_t*)&B1[n*72 + k];
                uint32_t b11 = *(const uint32_t*)&B1[n*72 + k + 8];
                uint32_t b20 = *(const uint32_t*)&B2[n*72 + k];
                uint32_t b21 = *(const uint32_t*)&B2[n*72 + k + 8];
                #pragma unroll
                for (int mi = 0; mi < 2; ++mi) {
                    mma_bf16(d[mi][ni], a1[mi][0], a1[mi][1], a1[mi][2], a1[mi][3], b10, b11);
                    mma_bf16(d[mi][ni], a1[mi][0], a1[mi][1], a1[mi][2], a1[mi][3], b20, b21);
                    mma_bf16(d[mi][ni], a2[mi][0], a2[mi][1], a2[mi][2], a2[mi][3], b10, b11);
                }
            }
        }
    }
    #pragma unroll
    for (int mi = 0; mi < 2; ++mi) {
        #pragma unroll
        for (int rr = 0; rr < 2; ++rr) {
            int s = blk*32 + mi*16 + gr + rr*8;
            int iv = svs[mi*16 + gr + rr*8];
            #pragma unroll
            for (int ni = 0; ni < 2; ++ni) {
                int c = w*16 + ni*8 + (lane & 3)*2;
                float2 cbv = *(const float2*)&g_cb[c];
                float2 ipv = *(const float2*)&ip[(size_t)iv*DD + c];
                float e0 = d[mi][ni][rr*2]   - cbv.x + ipv.x;
                float e1 = d[mi][ni][rr*2+1] - cbv.y + ipv.y;
                uint32_t hi, lo;
                split2(e0, e1, hi, lo);
                *(uint32_t*)&g_IFB[(size_t)s*K1 + DD + c]        = hi;
                *(uint32_t*)&g_IFB[(size_t)(BB + s)*K1 + DD + c] = lo;
            }
        }
    }
}

// ---------------- hu body: per chunk stage {A, B1, B2}, 2 term-groups ---------------
__device__ __forceinline__ void hu_body(char* sm, int blk,
                                        const int* __restrict__ nodes_d,
                                        const float* __restrict__ dp,
                                        float* __restrict__ out_hu) {
    MMA_DECL;
    auto stage = [&](int ch, int b) {
        char* base = sm + b*HU_BUF;
        int kk = ch * BK;
        const char* asrc = (const char*)g_maskh4
                         + (size_t)(blk*32 + (tid >> 3))*2048 + kk*2 + (tid & 7)*16;
        cpa16(base + (tid >> 3)*144 + (tid & 7)*16, asrc);
        #pragma unroll
        for (int sb = 0; sb < 2; ++sb) {
            char* Bd = base + 2*TA_SZ + sb*TB_SZ;
            const char* bbase = (const char*)g_PB2 + ((size_t)sb << 18);
            #pragma unroll
            for (int i = 0; i < 4; ++i) {
                int idx = tid + i*256; int c = idx >> 3, pc = idx & 7;
                cpa16(Bd + c*144 + pc*16, bbase + (size_t)c*2048 + kk*2 + pc*16);
            }
        }
        cpa_commit();
    };

    const int NCH = PROTO/BK;  // 16
    stage(0, 0);
    #pragma unroll 1
    for (int ch = 0; ch < NCH; ++ch) {
        __syncthreads();
        if (ch + 1 < NCH) { stage(ch + 1, (ch + 1) & 1); cpa_wait1(); }
        else cpa_wait0();
        __syncthreads();
        const char* base = sm + (ch & 1)*HU_BUF;
        const __nv_bfloat16* A  = (const __nv_bfloat16*)base;
        const __nv_bfloat16* B1 = (const __nv_bfloat16*)(base + 2*TA_SZ);
        const __nv_bfloat16* B2 = (const __nv_bfloat16*)(base + 2*TA_SZ + TB_SZ);
        #pragma unroll
        for (int ks = 0; ks < BK/16; ++ks) {
            int k = ks*16 + kb;
            uint32_t a[2][4];
            #pragma unroll
            for (int mi = 0; mi < 2; ++mi) {
                int r0 = mi*16 + gr;
                LOAD_A(a[mi], A, r0, k);
            }
            #pragma unroll
            for (int ni = 0; ni < 2; ++ni) {
                int n = w*16 + ni*8 + gr;
                uint32_t b10 = *(const uint32_t*)&B1[n*72 + k];
                uint32_t b11 = *(const uint32_t*)&B1[n*72 + k + 8];
                uint32_t b20 = *(const uint32_t*)&B2[n*72 + k];
                uint32_t b21 = *(const uint32_t*)&B2[n*72 + k + 8];
                #pragma unroll
                for (int mi = 0; mi < 2; ++mi) {
                    mma_bf16(d[mi][ni], a[mi][0], a[mi][1], a[mi][2], a[mi][3], b10, b11);
                    mma_bf16(d[mi][ni], a[mi][0], a[mi][1], a[mi][2], a[mi][3], b20, b21);
                }
            }
        }
    }
    #pragma unroll
    for (int mi = 0; mi < 2; ++mi) {
        #pragma unroll
        for (int rr = 0; rr < 2; ++rr) {
            int s = blk*32 + mi*16 + gr + rr*8;
            float inv = g_cinv[s];
            const float* pdr = dp + nodes_d[s]*DD;
            #pragma unroll
            for (int ni = 0; ni < 2; ++ni) {
                int c = w*16 + ni*8 + (lane & 3)*2;
                float h0 = d[mi][ni][rr*2]   * inv;
                float h1 = d[mi][ni][rr*2+1] * inv;
                *(float2*)&out_hu[s*DD + c] = make_float2(h0, h1);
                float2 pd = *(const float2*)&pdr[c];
                uint32_t hi, lo;
                split2(h0 + pd.x, h1 + pd.y, hi, lo);
                *(uint32_t*)&g_IFB[(size_t)s*K1 + c]        = hi;
                *(uint32_t*)&g_IFB[(size_t)(BB + s)*K1 + c] = lo;
            }
        }
    }
}

// fused: blocks [0,128) do e, [128,256) do hu
__global__ void __launch_bounds__(256) k_eh(const int* __restrict__ nodes_v,
                                            const float* __restrict__ pre_text,
                                            const float* __restrict__ pre_visual,
                                            const float* __restrict__ ip,
                                            const int* __restrict__ nodes_d,
                                            const float* __restrict__ dp,
                                            float* __restrict__ out_hu) {
    extern __shared__ char sm[];
    if (blockIdx.x < 128) e_body(sm, blockIdx.x, nodes_v, pre_text, pre_visual, ip);
    else                  hu_body(sm, blockIdx.x - 128, nodes_d, dp, out_hu);
}

// ===================================================================================
// k_tail: persistent fused z1 -> (gridsync) -> z2 -> (gridsync) -> pred.
// ===================================================================================
#define Z1_ST    264
#define Z1_ROWB  528
#define Z1_AOFF  0
#define Z1_BOFF  (64*Z1_ROWB)
#define ZW2_OFF  (64*Z1_ROWB + 256*Z1_ROWB)   // 168960
#define ZT_SMEM  (ZW2_OFF + 32768)            // 201728

__global__ void __launch_bounds__(256) k_tail(const float* __restrict__ b1,
                                              const float* __restrict__ b2,
                                              const float* __restrict__ g1,
                                              const float* __restrict__ be1,
                                              const float* __restrict__ W2,
                                              const float* __restrict__ g2,
                                              const float* __restrict__ be2,
                                              const float* __restrict__ Wp,
                                              const float* __restrict__ bp,
                                              float* __restrict__ out_pred) {
    extern __shared__ char sm[];
    __shared__ float A1s[DD], D1s[DD], bc[D2];
    __shared__ float z2s[32][D2];
    __shared__ float A2s[D2], D2s[D2];
    int blk = blockIdx.x;
    int tid = threadIdx.x;
    int w = tid >> 5, lane = tid & 31;
    int gr = lane >> 2, kb = (lane & 3) * 2;

    // ---------------- Phase 1: z1 = relu(IF @ W1^T + b1), BN1 partial stats --------
    float d[2][2][4];
    #pragma unroll
    for (int mi = 0; mi < 2; ++mi)
        #pragma unroll
        for (int ni = 0; ni < 2; ++ni)
            #pragma unroll
            for (int q = 0; q < 4; ++q) d[mi][ni][q] = 0.f;
    {
        #pragma unroll
        for (int i = 0; i < 8; ++i) {
            int idx = tid + i*256;
            int r = idx >> 5, pc = idx & 31;
            int sa = r >> 5, smp = r & 31;
            const char* src = (const char*)g_IFB + (size_t)sa*BB*K1*2
                            + (size_t)(blk*32 + smp)*(K1*2) + pc*16;
            cpa16(sm + Z1_AOFF + r*Z1_ROWB + pc*16, src);
        }
        #pragma unroll
        for (int i = 0; i < 32; ++i) {
            int idx = tid + i*256;
            int r = idx >> 5, pc = idx & 31;
            const char* src = (const char*)g_W1B2 + (size_t)r*(K1*2) + pc*16;
            cpa16(sm + Z1_BOFF + r*Z1_ROWB + pc*16, src);
        }
        #pragma unroll
        for (int i = 0; i < 8; ++i) {      // W2 fp32: 2048 x 16B
            int idx = tid + i*256;
            cpa16(sm + ZW2_OFF + idx*16, (const char*)W2 + idx*16);
        }
        cpa_commit();
    }
    cpa_wait0();
    __syncthreads();
    #pragma unroll 1
    for (int ch = 0; ch < 12; ++ch) {
        int seg = ch >> 2;
        int k0 = (ch & 3) * BK;
        int sa = (seg == 2) ? 1 : 0;
        int sb = (seg == 1) ? 1 : 0;
        const __nv_bfloat16* A = (const __nv_bfloat16*)(sm + Z1_AOFF + sa*32*Z1_ROWB) + k0;
        const __nv_bfloat16* B = (const __nv_bfloat16*)(sm + Z1_BOFF + sb*128*Z1_ROWB) + k0;
        #pragma unroll
        for (int ks = 0; ks < BK/16; ++ks) {
            int k = ks*16 + kb;
            #pragma unroll
            for (int mi = 0; mi < 2; ++mi) {
                int r0 = mi*16 + gr;
                uint32_t a0 = *(const uint32_t*)&A[r0*Z1_ST + k];
                uint32_t a1 = *(const uint32_t*)&A[(r0+8)*Z1_ST + k];
                uint32_t a2 = *(const uint32_t*)&A[r0*Z1_ST + k + 8];
                uint32_t a3 = *(const uint32_t*)&A[(r0+8)*Z1_ST + k + 8];
                #pragma unroll
                for (int ni = 0; ni < 2; ++ni) {
                    int n = w*16 + ni*8 + gr;
                    uint32_t b0 = *(const uint32_t*)&B[n*Z1_ST + k];
                    uint32_t b1v = *(const uint32_t*)&B[n*Z1_ST + k + 8];
                    mma_bf16(d[mi][ni], a0, a1, a2, a3, b0, b1v);
                }
            }
        }
    }
    __syncthreads();   // all MMAs done -> safe to overwrite A region with z1 splits
    {
        float2 bb0 = *(const float2*)&b1[w*16 + (lane & 3)*2];
        float2 bb1 = *(const float2*)&b1[w*16 + 8 + (lane & 3)*2];
        float ps[2][2] = {{0,0},{0,0}}, pq[2][2] = {{0,0},{0,0}};
        #pragma unroll
        for (int mi = 0; mi < 2; ++mi) {
            #pragma unroll
            for (int rr = 0; rr < 2; ++rr) {
                int sl = mi*16 + gr + rr*8;
                #pragma unroll
                for (int ni = 0; ni < 2; ++ni) {
                    int c = w*16 + ni*8 + (lane & 3)*2;
                    float bbx = ni ? bb1.x : bb0.x, bby = ni ? bb1.y : bb0.y;
                    float z0 = d[mi][ni][rr*2]   + bbx; z0 = z0 > 0.f ? z0 : 0.f;
                    float z1v = d[mi][ni][rr*2+1] + bby; z1v = z1v > 0.f ? z1v : 0.f;
                    uint32_t hi, lo;
                    split2(z0, z1v, hi, lo);
                    *(uint32_t*)(sm + Z1_AOFF + sl*Z1_ROWB + c*2)              = hi;
                    *(uint32_t*)(sm + Z1_AOFF + (32 + sl)*Z1_ROWB + c*2)       = lo;
                    ps[ni][0] += z0; ps[ni][1] += z1v;
                    pq[ni][0] += z0*z0; pq[ni][1] += z1v*z1v;
                }
            }
        }
        #pragma unroll
        for (int ni = 0; ni < 2; ++ni) {
            #pragma unroll
            for (int q = 0; q < 2; ++q) {
                #pragma unroll
                for (int o = 4; o <= 16; o <<= 1) {
                    ps[ni][q] += __shfl_xor_sync(0xffffffffu, ps[ni][q], o);
                    pq[ni][q] += __shfl_xor_sync(0xffffffffu, pq[ni][q], o);
                }
            }
            if (lane < 4) {
                int c = w*16 + ni*8 + lane*2;
                atomicAdd(&g_s1[c],   ps[ni][0]); atomicAdd(&g_s1[c+1], ps[ni][1]);
                atomicAdd(&g_q1[c],   pq[ni][0]); atomicAdd(&g_q1[c+1], pq[ni][1]);
            }
        }
    }
    gsync(&g_bar1, 128);

    // ---------------- Phase 2: z2 = relu( z1 @ (W2.*A1)^T + (D1@W2^T + b2) ) -------
    if (tid < DD) {
        float m = __ldcg(&g_s1[tid]) * (1.0f/BB);
        float v = __ldcg(&g_q1[tid]) * (1.0f/BB) - m*m;
        float r = rsqrtf(v + 1e-5f);
        float a = g1[tid] * r;
        A1s[tid] = a;
        D1s[tid] = be1[tid] - m*a;
    }
    __syncthreads();
    {   // fold W2 (from smem fp32) into B region as bf16 splits; compute bconst
        int c = tid >> 2, q = tid & 3;
        const float* wrow = (const float*)(sm + ZW2_OFF) + c*DD + q*32;
        __nv_bfloat16* Bh = (__nv_bfloat16*)(sm + Z1_BOFF + c*Z1_ROWB) + q*32;
        __nv_bfloat16* Bl = (__nv_bfloat16*)(sm + Z1_BOFF + (64 + c)*Z1_ROWB) + q*32;
        float bacc = 0.f;
        #pragma unroll
        for (int j = 0; j < 16; ++j) {
            int k = q*32 + 2*j;
            float w0 = wrow[2*j],  w1 = wrow[2*j+1];
            bacc += D1s[k]*w0 + D1s[k+1]*w1;
            float f0 = w0 * A1s[k], f1 = w1 * A1s[k+1];
            uint32_t hi, lo;
            split2(f0, f1, hi, lo);
            *(uint32_t*)&Bh[2*j] = hi;
            *(uint32_t*)&Bl[2*j] = lo;
        }
        bacc += __shfl_down_sync(0xffffffffu, bacc, 1);
        bacc += __shfl_down_sync(0xffffffffu, bacc, 2);
        if (q == 0) bc[c] = bacc + b2[c];
    }
    __syncthreads();
    float d2[2][4];
    #pragma unroll
    for (int mi = 0; mi < 2; ++mi)
        #pragma unroll
        for (int q = 0; q < 4; ++q) d2[mi][q] = 0.f;
    #pragma unroll 1
    for (int seg = 0; seg < 3; ++seg) {
        int sa = (seg == 2) ? 1 : 0;
        int sb = (seg == 1) ? 1 : 0;
        const __nv_bfloat16* A = (const __nv_bfloat16*)(sm + Z1_AOFF + sa*32*Z1_ROWB);
        const __nv_bfloat16* B = (const __nv_bfloat16*)(sm + Z1_BOFF + sb*64*Z1_ROWB);
        #pragma unroll
        for (int ks = 0; ks < DD/16; ++ks) {
            int k = ks*16 + kb;
            int n = w*8 + gr;
            uint32_t b0 = *(const uint32_t*)&B[n*Z1_ST + k];
            uint32_t b1v = *(const uint32_t*)&B[n*Z1_ST + k + 8];
            #pragma unroll
            for (int mi = 0; mi < 2; ++mi) {
                int r0 = mi*16 + gr;
                uint32_t a0 = *(const uint32_t*)&A[r0*Z1_ST + k];
                uint32_t a1 = *(const uint32_t*)&A[(r0+8)*Z1_ST + k];
                uint32_t a2 = *(const uint32_t*)&A[r0*Z1_ST + k + 8];
                uint32_t a3 = *(const uint32_t*)&A[(r0+8)*Z1_ST + k + 8];
                mma_bf16(d2[mi], a0, a1, a2, a3, b0, b1v);
            }
        }
    }
    {
        int c0 = w*8 + (lane & 3)*2;
        float2 bcv = *(const float2*)&bc[c0];
        float ps0 = 0.f, ps1 = 0.f, pq0 = 0.f, pq1 = 0.f;
        #pragma unroll
        for (int mi = 0; mi < 2; ++mi) {
            #pragma unroll
            for (int rr = 0; rr < 2; ++rr) {
                int sl = mi*16 + gr + rr*8;
                float z0 = d2[mi][rr*2]   + bcv.x; z0 = z0 > 0.f ? z0 : 0.f;
                float z1v = d2[mi][rr*2+1] + bcv.y; z1v = z1v > 0.f ? z1v : 0.f;
                z2s[sl][c0] = z0;  z2s[sl][c0+1] = z1v;
                ps0 += z0; ps1 += z1v; pq0 += z0*z0; pq1 += z1v*z1v;
            }
        }
        #pragma unroll
        for (int o = 4; o <= 16; o <<= 1) {
            ps0 += __shfl_xor_sync(0xffffffffu, ps0, o);
            ps1 += __shfl_xor_sync(0xffffffffu, ps1, o);
            pq0 += __shfl_xor_sync(0xffffffffu, pq0, o);
            pq1 += __shfl_xor_sync(0xffffffffu, pq1, o);
        }
        if (lane < 4) {
            atomicAdd(&g_s2[c0],   ps0); atomicAdd(&g_s2[c0+1], ps1);
            atomicAdd(&g_q2[c0],   pq0); atomicAdd(&g_q2[c0+1], pq1);
        }
    }
    gsync(&g_bar2, 128);

    // ---------------- Phase 3: pred = sigmoid(BN(z2) @ Wp^T + bp) ------------------
    if (tid < D2) {
        float m = __ldcg(&g_s2[tid]) * (1.0f/BB);
        float v = __ldcg(&g_q2[tid]) * (1.0f/BB) - m*m;
        float r = rsqrtf(v + 1e-5f);
        float a = g2[tid] * r;
        A2s[tid] = a;
        D2s[tid] = be2[tid] - m*a;
    }
    __syncthreads();
    {
        int c = lane*2;
        float2 wp = *(const float2*)&Wp[c];
        float a0 = A2s[c], a1 = A2s[c+1], dd0 = D2s[c], dd1 = D2s[c+1];
        float bpv = bp[0];
        #pragma unroll
        for (int i = 0; i < 4; ++i) {
            int sl = w*4 + i;
            float t = (z2s[sl][c]*a0 + dd0)*wp.x + (z2s[sl][c+1]*a1 + dd1)*wp.y;
            #pragma unroll
            for (int o = 16; o; o >>= 1) t += __shfl_down_sync(0xffffffffu, t, o);
            if (lane == 0)
                out_pred[blk*32 + sl] = 1.0f / (1.0f + expf(-(t + bpv)));
        }
    }
}

// ---------------- launch ------------------------------------------------------------
extern "C" void kernel_launch(void* const* d_in, const int* in_sizes, int n_in,
                              void* d_out, int out_size) {
    const int*   nodes_u     = (const int*)  d_in[0];
    const int*   nodes_v     = (const int*)  d_in[1];
    const int*   nodes_d     = (const int*)  d_in[2];
    const int*   inter_items = (const int*)  d_in[3];
    const int*   top_n       = (const int*)  d_in[4];
    const float* protos      = (const float*)d_in[5];
    const float* pre_text    = (const float*)d_in[6];
    const float* pre_visual  = (const float*)d_in[7];
    const float* Wt          = (const float*)d_in[8];
    const float* bt          = (const float*)d_in[9];
    const float* Wv          = (const float*)d_in[10];
    const float* bv          = (const float*)d_in[11];
    const float* up          = (const float*)d_in[12];
    const float* ip          = (const float*)d_in[13];
    const float* dp          = (const float*)d_in[14];
    const float* W1          = (const float*)d_in[15];
    const float* b1          = (const float*)d_in[16];
    const float* g1          = (const float*)d_in[17];
    const float* be1         = (const float*)d_in[18];
    const float* W2          = (const float*)d_in[19];
    const float* b2          = (const float*)d_in[20];
    const float* g2          = (const float*)d_in[21];
    const float* be2         = (const float*)d_in[22];
    const float* Wp          = (const float*)d_in[23];
    const float* bp          = (const float*)d_in[24];

    float* out      = (float*)d_out;
    float* out_pred = out;
    float* out_pu   = out + BB;
    float* out_hu   = out + BB + BB*DD;
    float* out_pd   = out + BB + 2*BB*DD;

    cudaFuncSetAttribute(k_eh,   cudaFuncAttributeMaxDynamicSharedMemorySize, EH_SMEM);
    cudaFuncSetAttribute(k_tail, cudaFuncAttributeMaxDynamicSharedMemorySize, ZT_SMEM);

    k_xp<<<BB + 328, 128>>>(nodes_u, nodes_v, nodes_d, inter_items, top_n,
                            up, dp, out_pu, out_pd,
                            Wt, Wv, W1, protos, bt, bv);
    k_eh<<<256, 256, EH_SMEM>>>(nodes_v, pre_text, pre_visual, ip, nodes_d, dp, out_hu);
    k_tail<<<128, 256, ZT_SMEM>>>(b1, b2, g1, be1, W2, g2, be2, Wp, bp, out_pred);
}

// round 17
// speedup vs baseline: 1.0075x; 1.0075x over previous
#include <cuda_runtime.h>
#include <cuda_bf16.h>
#include <cstdint>

// Problem constants
#define BB    4096
#define DD    128
#define HIST  50
#define TOPN  4
#define PROTO 1024
#define ITEMS 100000
#define KTOT  1152      // 384 text + 768 visual
#define K1    256       // MLP layer1 input
#define D2    64        // MLP layer2 output

typedef unsigned long long ull;

// ---------------- scratch (__device__ globals; no allocation allowed) ----------------
__device__ float  g_cb[DD];             // bt·Wt_row + bv·Wv_row
__device__ __align__(16) __nv_bfloat16 g_PB2[2*128*1024];  // bf16 split protos^T [split][c][k]
__device__ __align__(16) __nv_bfloat16 g_WB2[2*128*KTOT];  // bf16 split [Wt|Wv]  [split][c][k]
__device__ __align__(16) __nv_bfloat16 g_W1B2[2*128*K1];   // bf16 split W1       [split][c][k]
__device__ __align__(16) __nv_bfloat16 g_IFB[2*BB*K1];     // bf16 split inter_feat
__device__ float  g_s1[DD], g_q1[DD];
__device__ float  g_s2[D2], g_q2[D2];
__device__ int    g_bar1, g_bar2;       // grid-barrier counters (reset each call)

__device__ __forceinline__ void cpa16(void* dst, const void* src) {
    unsigned d = (unsigned)__cvta_generic_to_shared(dst);
    asm volatile("cp.async.cg.shared.global [%0], [%1], 16;" :: "r"(d), "l"(src));
}
__device__ __forceinline__ void cpa_commit() { asm volatile("cp.async.commit_group;"); }
__device__ __forceinline__ void cpa_wait1() { asm volatile("cp.async.wait_group 1;"); }
__device__ __forceinline__ void cpa_wait0() { asm volatile("cp.async.wait_group 0;"); }

// HMMA bf16: D(f32) += A(bf16 m16k16 row) * B(bf16 k16n8 col)
__device__ __forceinline__ void mma_bf16(float* d, uint32_t a0, uint32_t a1,
                                         uint32_t a2, uint32_t a3,
                                         uint32_t b0, uint32_t b1) {
    asm volatile("mma.sync.aligned.m16n8k16.row.col.f32.bf16.bf16.f32 "
                 "{%0,%1,%2,%3},{%4,%5,%6,%7},{%8,%9},{%0,%1,%2,%3};"
                 : "+f"(d[0]), "+f"(d[1]), "+f"(d[2]), "+f"(d[3])
                 : "r"(a0), "r"(a1), "r"(a2), "r"(a3), "r"(b0), "r"(b1));
}
__device__ __forceinline__ uint32_t pk_bf2(float lo, float hi) {
    uint32_t r;
    asm("cvt.rn.bf16x2.f32 %0, %1, %2;" : "=r"(r) : "f"(hi), "f"(lo));
    return r;
}
__device__ __forceinline__ void split2(float v0, float v1, uint32_t &hi, uint32_t &lo) {
    __nv_bfloat16 h0 = __float2bfloat16(v0), h1 = __float2bfloat16(v1);
    uint16_t u0, u1; memcpy(&u0, &h0, 2); memcpy(&u1, &h1, 2);
    hi = (uint32_t)u0 | ((uint32_t)u1 << 16);
    lo = pk_bf2(v0 - __bfloat162float(h0), v1 - __bfloat162float(h1));
}

// grid barrier: all CTAs co-resident (grid=128 <= 148 SMs, 1 CTA/SM)
__device__ __forceinline__ void gsync(int* bar, int target) {
    __syncthreads();
    if (threadIdx.x == 0) {
        __threadfence();
        atomicAdd(bar, 1);
        while (atomicAdd(bar, 0) < target) { }
        __threadfence();
    }
    __syncthreads();
}

// ---------------- k_prep: weight splits + cb + zero stats (weights only) ------------
__global__ void __launch_bounds__(128) k_prep(
        const float* __restrict__ Wt, const float* __restrict__ Wv,
        const float* __restrict__ W1,
        const float* __restrict__ protos,
        const float* __restrict__ bt, const float* __restrict__ bv) {
    int blk = blockIdx.x, tid = threadIdx.x;
    if (blk >= 296) {   // cb part: 32 blocks x 4 warps = 128 columns
        int c = (blk - 296)*4 + (tid >> 5);
        int l = tid & 31;
        float s = 0.f;
        for (int k = l; k < 384; k += 32) s += bt[k] * Wt[c*384 + k];
        for (int k = l; k < 768; k += 32) s += bv[k] * Wv[c*768 + k];
        #pragma unroll
        for (int o = 16; o; o >>= 1) s += __shfl_down_sync(0xffffffffu, s, o);
        if (l == 0) g_cb[c] = s;
        return;
    }
    const int n_wb = 128*KTOT;
    const int n_pb = 128*1024;
    const int n_w1 = 128*K1;
    const int n_z  = 2*DD + 2*D2 + 2;
    int total = n_wb + n_pb + n_w1 + n_z;
    for (int i = blk*128 + tid; i < total; i += 296*128) {
        if (i < n_wb) {
            int c = i / KTOT, k = i % KTOT;
            float v = (k < 384) ? Wt[c*384 + k] : Wv[c*768 + (k - 384)];
            __nv_bfloat16 b1 = __float2bfloat16(v);
            g_WB2[i]            = b1;
            g_WB2[128*KTOT + i] = __float2bfloat16(v - __bfloat162float(b1));
        } else if (i < n_wb + n_pb) {
            int j = i - n_wb; int c = j & 127; int k = j >> 7;
            float p = protos[k*DD + c];
            __nv_bfloat16 b1 = __float2bfloat16(p);
            g_PB2[c*1024 + k]          = b1;
            g_PB2[131072 + c*1024 + k] = __float2bfloat16(p - __bfloat162float(b1));
        } else if (i < n_wb + n_pb + n_w1) {
            int j = i - n_wb - n_pb;
            float v = W1[j];
            __nv_bfloat16 b1 = __float2bfloat16(v);
            g_W1B2[j]          = b1;
            g_W1B2[128*K1 + j] = __float2bfloat16(v - __bfloat162float(b1));
        } else {
            int j = i - n_wb - n_pb - n_w1;
            if (j < DD)               g_s1[j] = 0.f;
            else if (j < 2*DD)        g_q1[j-DD] = 0.f;
            else if (j < 2*DD+D2)     g_s2[j-2*DD] = 0.f;
            else if (j < 2*DD+2*D2)   g_q2[j-2*DD-D2] = 0.f;
            else if (j == 2*DD+2*D2)  g_bar1 = 0;
            else                      g_bar2 = 0;
        }
    }
}

// ===================================================================================
// HMMA GEMM: M=32 x N=128, BK=64, depth-2 pipeline.
// e  buffer: [Af32 32x272][Ahi 32x144][Alo 32x144][Bhi 128x144][Blo 128x144] = 54784
// hu buffer: [A 32x144][Bhi 128x144][Blo 128x144] = 41472 (A expanded from bitmask)
// ===================================================================================
#define BK     64
#define TA_SZ  (32*144)
#define TB_SZ  (128*144)
#define AF_SZ  (32*272)
#define AH_OFF AF_SZ                    // 8704
#define AL_OFF (AF_SZ + TA_SZ)          // 13312
#define EB_OFF (AF_SZ + 2*TA_SZ)        // 17920
#define E_BUF  (EB_OFF + 2*TB_SZ)       // 54784
#define HU_BUF (TA_SZ + 2*TB_SZ)        // 41472
#define EH_SMEM (2*E_BUF)               // 109568

#define MMA_DECL                                                                \
    int tid = threadIdx.x;                                                      \
    int w = tid >> 5, lane = tid & 31;                                          \
    int gr = lane >> 2, kb = (lane & 3) * 2;                                    \
    float d[2][2][4];                                                           \
    _Pragma("unroll")                                                           \
    for (int mi = 0; mi < 2; ++mi)                                              \
        _Pragma("unroll")                                                       \
        for (int ni = 0; ni < 2; ++ni)                                          \
            _Pragma("unroll")                                                   \
            for (int q = 0; q < 4; ++q) d[mi][ni][q] = 0.f;

#define LOAD_A(dst, SRC, r0, k)                                                 \
    dst[0] = *(const uint32_t*)&SRC[(r0)*72 + (k)];                             \
    dst[1] = *(const uint32_t*)&SRC[((r0)+8)*72 + (k)];                         \
    dst[2] = *(const uint32_t*)&SRC[(r0)*72 + (k) + 8];                         \
    dst[3] = *(const uint32_t*)&SRC[((r0)+8)*72 + (k) + 8];

// ---------------- e body: direct fp32 gather + in-smem split, 3 term-groups --------
__device__ __forceinline__ void e_body(char* sm, int* svs, int blk,
                                       const int* __restrict__ nodes_v,
                                       const float* __restrict__ pre_text,
                                       const float* __restrict__ pre_visual,
                                       const float* __restrict__ ip) {
    MMA_DECL;
    if (tid < 32) svs[tid] = nodes_v[blk*32 + tid];
    __syncthreads();

    auto stage = [&](int ch, int b) {
        char* base = sm + b*E_BUF;
        int kk = ch * BK;
        #pragma unroll
        for (int i = 0; i < 2; ++i) {
            int idx = tid + i*256; int r = idx >> 4, pc = idx & 15;
            int row = svs[r];
            const char* src = (kk < 384)
                ? (const char*)(pre_text + (size_t)row*384 + kk) + pc*16
                : (const char*)(pre_visual + (size_t)row*768 + (kk - 384)) + pc*16;
            cpa16(base + r*272 + pc*16, src);
        }
        #pragma unroll
        for (int sb = 0; sb < 2; ++sb) {
            char* Bd = base + EB_OFF + sb*TB_SZ;
            const char* bbase = (const char*)g_WB2 + (size_t)sb*128*KTOT*2;
            #pragma unroll
            for (int i = 0; i < 4; ++i) {
                int idx = tid + i*256; int c = idx >> 3, pc = idx & 7;
                cpa16(Bd + c*144 + pc*16, bbase + (size_t)c*(KTOT*2) + kk*2 + pc*16);
            }
        }
        cpa_commit();
    };

    const int NCH = KTOT/BK;   // 18
    stage(0, 0);
    #pragma unroll 1
    for (int ch = 0; ch < NCH; ++ch) {
        __syncthreads();
        if (ch + 1 < NCH) { stage(ch + 1, (ch + 1) & 1); cpa_wait1(); }
        else cpa_wait0();
        __syncthreads();
        char* base = sm + (ch & 1)*E_BUF;
        {
            const float* Af = (const float*)base;
            __nv_bfloat16* Ah = (__nv_bfloat16*)(base + AH_OFF);
            __nv_bfloat16* Al = (__nv_bfloat16*)(base + AL_OFF);
            int r = tid >> 3, j = tid & 7;
            const float* p = Af + r*68 + j*8;
            uint32_t hh[4], ll[4];
            #pragma unroll
            for (int q = 0; q < 4; ++q) split2(p[2*q], p[2*q+1], hh[q], ll[q]);
            *(uint4*)&Ah[r*72 + j*8] = make_uint4(hh[0], hh[1], hh[2], hh[3]);
            *(uint4*)&Al[r*72 + j*8] = make_uint4(ll[0], ll[1], ll[2], ll[3]);
        }
        __syncthreads();
        const __nv_bfloat16* A1 = (const __nv_bfloat16*)(base + AH_OFF);
        const __nv_bfloat16* A2 = (const __nv_bfloat16*)(base + AL_OFF);
        const __nv_bfloat16* B1 = (const __nv_bfloat16*)(base + EB_OFF);
        const __nv_bfloat16* B2 = (const __nv_bfloat16*)(base + EB_OFF + TB_SZ);
        #pragma unroll
        for (int ks = 0; ks < BK/16; ++ks) {
            int k = ks*16 + kb;
            uint32_t a1[2][4], a2[2][4];
            #pragma unroll
            for (int mi = 0; mi < 2; ++mi) {
                int r0 = mi*16 + gr;
                LOAD_A(a1[mi], A1, r0, k);
                LOAD_A(a2[mi], A2, r0, k);
            }
            #pragma unroll
            for (int ni = 0; ni < 2; ++ni) {
                int n = w*16 + ni*8 + gr;
                uint32_t b10 = *(const uint32_t*)&B1[n*72 + k];
                uint32_t b11 = *(const uint32_t*)&B1[n*72 + k + 8];
                uint32_t b20 = *(const uint32_t*)&B2[n*72 + k];
                uint32_t b21 = *(const uint32_t*)&B2[n*72 + k + 8];
                #pragma unroll
                for (int mi = 0; mi < 2; ++mi) {
                    mma_bf16(d[mi][ni], a1[mi][0], a1[mi][1], a1[mi][2], a1[mi][3], b10, b11);
                    mma_bf16(d[mi][ni], a1[mi][0], a1[mi][1], a1[mi][2], a1[mi][3], b20, b21);
                    mma_bf16(d[mi][ni], a2[mi][0], a2[mi][1], a2[mi][2], a2[mi][3], b10, b11);
                }
            }
        }
    }
    #pragma unroll
    for (int mi = 0; mi < 2; ++mi) {
        #pragma unroll
        for (int rr = 0; rr < 2; ++rr) {
            int s = blk*32 + mi*16 + gr + rr*8;
            int iv = svs[mi*16 + gr + rr*8];
            #pragma unroll
            for (int ni = 0; ni < 2; ++ni) {
                int c = w*16 + ni*8 + (lane & 3)*2;
                float2 cbv = *(const float2*)&g_cb[c];
                float2 ipv = *(const float2*)&ip[(size_t)iv*DD + c];
                float e0 = d[mi][ni][rr*2]   - cbv.x + ipv.x;
                float e1 = d[mi][ni][rr*2+1] - cbv.y + ipv.y;
                uint32_t hi, lo;
                split2(e0, e1, hi, lo);
                *(uint32_t*)&g_IFB[(size_t)s*K1 + DD + c]        = hi;
                *(uint32_t*)&g_IFB[(size_t)(BB + s)*K1 + DD + c] = lo;
            }
        }
    }
}

// ---------------- hu body: inline mask build + bit-expanded A, 2 term-groups --------
__device__ __forceinline__ void hu_body(char* sm, unsigned (*bm)[32],
                                        float* cinvs, int* snd, int* snu, int blk,
                                        const int* __restrict__ nodes_u,
                                        const int* __restrict__ nodes_d,
                                        const int* __restrict__ inter_items,
                                        const int* __restrict__ top_n,
                                        const float* __restrict__ up,
                                        const float* __restrict__ dp,
                                        float* __restrict__ out_pu,
                                        float* __restrict__ out_pd,
                                        float* __restrict__ out_hu) {
    MMA_DECL;
    // init bitmask + sample meta
    for (int i = tid; i < 32*32; i += 256) ((unsigned*)bm)[i] = 0u;
    if (tid < 32) {
        snd[tid] = nodes_d[blk*32 + tid];
        snu[tid] = nodes_u[blk*32 + tid];
    }
    __syncthreads();

    auto stageB = [&](int ch, int b) {
        char* base = sm + b*HU_BUF;
        int kk = ch * BK;
        #pragma unroll
        for (int sb = 0; sb < 2; ++sb) {
            char* Bd = base + TA_SZ + sb*TB_SZ;
            const char* bbase = (const char*)g_PB2 + ((size_t)sb << 18);
            #pragma unroll
            for (int i = 0; i < 4; ++i) {
                int idx = tid + i*256; int c = idx >> 3, pc = idx & 7;
                cpa16(Bd + c*144 + pc*16, bbase + (size_t)c*2048 + kk*2 + pc*16);
            }
        }
        cpa_commit();
    };

    stageB(0, 0);                        // overlap mask gathers with first B stage
    // build bitmasks: 32 samples x 50 items, 2 x int4 gathers each
    const int4* tn4 = (const int4*)top_n;
    #pragma unroll 1
    for (int j = tid; j < 32*HIST; j += 256) {
        int sl = j / HIST, h = j - sl*HIST;
        int item = inter_items[(blk*32 + sl)*HIST + h];
        int4 r1 = tn4[item];
        int4 r2 = tn4[item + ITEMS];
        atomicOr(&bm[sl][r1.x >> 5], 1u << (r1.x & 31));
        atomicOr(&bm[sl][r1.y >> 5], 1u << (r1.y & 31));
        atomicOr(&bm[sl][r1.z >> 5], 1u << (r1.z & 31));
        atomicOr(&bm[sl][r1.w >> 5], 1u << (r1.w & 31));
        atomicOr(&bm[sl][r2.x >> 5], 1u << (r2.x & 31));
        atomicOr(&bm[sl][r2.y >> 5], 1u << (r2.y & 31));
        atomicOr(&bm[sl][r2.z >> 5], 1u << (r2.z & 31));
        atomicOr(&bm[sl][r2.w >> 5], 1u << (r2.w & 31));
    }
    __syncthreads();
    // counts: warp w handles samples w*4..w*4+3
    #pragma unroll
    for (int q = 0; q < 4; ++q) {
        int sl = w*4 + q;
        unsigned c = __popc(bm[sl][lane]);
        #pragma unroll
        for (int o = 16; o; o >>= 1) c += __shfl_down_sync(0xffffffffu, c, o);
        if (lane == 0) cinvs[sl] = 1.0f / (float)c;
    }

    const int NCH = PROTO/BK;  // 16
    #pragma unroll 1
    for (int ch = 0; ch < NCH; ++ch) {
        __syncthreads();
        // expand A(ch) from bitmask into buffer (ch&1): thread = row r x bit-octet j
        {
            char* base = sm + (ch & 1)*HU_BUF;
            int r = tid >> 3, j = tid & 7;
            unsigned word = bm[r][ch*2 + (j >> 2)];
            int sh = (j & 3) * 8;
            uint32_t pk[4];
            #pragma unroll
            for (int q = 0; q < 4; ++q) {
                uint32_t lo = ((word >> (sh + 2*q)) & 1) ? 0x3F80u : 0u;
                uint32_t hi = ((word >> (sh + 2*q + 1)) & 1) ? 0x3F80u : 0u;
                pk[q] = lo | (hi << 16);
            }
            *(uint4*)(base + r*144 + j*16) = make_uint4(pk[0], pk[1], pk[2], pk[3]);
        }
        if (ch + 1 < NCH) { stageB(ch + 1, (ch + 1) & 1); cpa_wait1(); }
        else cpa_wait0();
        __syncthreads();
        const char* base = sm + (ch & 1)*HU_BUF;
        const __nv_bfloat16* A  = (const __nv_bfloat16*)base;
        const __nv_bfloat16* B1 = (const __nv_bfloat16*)(base + TA_SZ);
        const __nv_bfloat16* B2 = (const __nv_bfloat16*)(base + TA_SZ + TB_SZ);
        #pragma unroll
        for (int ks = 0; ks < BK/16; ++ks) {
            int k = ks*16 + kb;
            uint32_t a[2][4];
            #pragma unroll
            for (int mi = 0; mi < 2; ++mi) {
                int r0 = mi*16 + gr;
                LOAD_A(a[mi], A, r0, k);
            }
            #pragma unroll
            for (int ni = 0; ni < 2; ++ni) {
                int n = w*16 + ni*8 + gr;
                uint32_t b10 = *(const uint32_t*)&B1[n*72 + k];
                uint32_t b11 = *(const uint32_t*)&B1[n*72 + k + 8];
                uint32_t b20 = *(const uint32_t*)&B2[n*72 + k];
                uint32_t b21 = *(const uint32_t*)&B2[n*72 + k + 8];
                #pragma unroll
                for (int mi = 0; mi < 2; ++mi) {
                    mma_bf16(d[mi][ni], a[mi][0], a[mi][1], a[mi][2], a[mi][3], b10, b11);
                    mma_bf16(d[mi][ni], a[mi][0], a[mi][1], a[mi][2], a[mi][3], b20, b21);
                }
            }
        }
    }
    #pragma unroll
    for (int mi = 0; mi < 2; ++mi) {
        #pragma unroll
        for (int rr = 0; rr < 2; ++rr) {
            int sl = mi*16 + gr + rr*8;
            int s = blk*32 + sl;
            float inv = cinvs[sl];
            const float* pdr = dp + snd[sl]*DD;
            const float* pur = up + (size_t)snu[sl]*DD;
            #pragma unroll
            for (int ni = 0; ni < 2; ++ni) {
                int c = w*16 + ni*8 + (lane & 3)*2;
                float h0 = d[mi][ni][rr*2]   * inv;
                float h1 = d[mi][ni][rr*2+1] * inv;
                *(float2*)&out_hu[s*DD + c] = make_float2(h0, h1);
                float2 pd = *(const float2*)&pdr[c];
                *(float2*)&out_pd[s*DD + c] = pd;
                *(float2*)&out_pu[s*DD + c] = *(const float2*)&pur[c];
                uint32_t hi, lo;
                split2(h0 + pd.x, h1 + pd.y, hi, lo);
                *(uint32_t*)&g_IFB[(size_t)s*K1 + c]        = hi;
                *(uint32_t*)&g_IFB[(size_t)(BB + s)*K1 + c] = lo;
            }
        }
    }
}

// fused: blocks [0,128) do e, [128,256) do hu
__global__ void __launch_bounds__(256) k_eh(const int* __restrict__ nodes_v,
                                            const float* __restrict__ pre_text,
                                            const float* __restrict__ pre_visual,
                                            const float* __restrict__ ip,
                                            const int* __restrict__ nodes_u,
                                            const int* __restrict__ nodes_d,
                                            const int* __restrict__ inter_items,
                                            const int* __restrict__ top_n,
                                            const float* __restrict__ up,
                                            const float* __restrict__ dp,
                                            float* __restrict__ out_pu,
                                            float* __restrict__ out_pd,
                                            float* __restrict__ out_hu) {
    extern __shared__ char sm[];
    __shared__ int svs[32];
    __shared__ unsigned bm[32][32];
    __shared__ float cinvs[32];
    __shared__ int snd[32], snu[32];
    if (blockIdx.x < 128)
        e_body(sm, svs, blockIdx.x, nodes_v, pre_text, pre_visual, ip);
    else
        hu_body(sm, bm, cinvs, snd, snu, blockIdx.x - 128,
                nodes_u, nodes_d, inter_items, top_n, up, dp,
                out_pu, out_pd, out_hu);
}

// ===================================================================================
// k_tail: persistent fused z1 -> (gridsync) -> z2 -> (gridsync) -> pred.
// ===================================================================================
#define Z1_ST    264
#define Z1_ROWB  528
#define Z1_AOFF  0
#define Z1_BOFF  (64*Z1_ROWB)
#define ZW2_OFF  (64*Z1_ROWB + 256*Z1_ROWB)   // 168960
#define ZT_SMEM  (ZW2_OFF + 32768)            // 201728

__global__ void __launch_bounds__(256) k_tail(const float* __restrict__ b1,
                                              const float* __restrict__ b2,
                                              const float* __restrict__ g1,
                                              const float* __restrict__ be1,
                                              const float* __restrict__ W2,
                                              const float* __restrict__ g2,
                                              const float* __restrict__ be2,
                                              const float* __restrict__ Wp,
                                              const float* __restrict__ bp,
                                              float* __restrict__ out_pred) {
    extern __shared__ char sm[];
    __shared__ float A1s[DD], D1s[DD], bc[D2];
    __shared__ float z2s[32][D2];
    __shared__ float A2s[D2], D2s[D2];
    int blk = blockIdx.x;
    int tid = threadIdx.x;
    int w = tid >> 5, lane = tid & 31;
    int gr = lane >> 2, kb = (lane & 3) * 2;

    // ---------------- Phase 1: z1 = relu(IF @ W1^T + b1), BN1 partial stats --------
    float d[2][2][4];
    #pragma unroll
    for (int mi = 0; mi < 2; ++mi)
        #pragma unroll
        for (int ni = 0; ni < 2; ++ni)
            #pragma unroll
            for (int q = 0; q < 4; ++q) d[mi][ni][q] = 0.f;
    {
        #pragma unroll
        for (int i = 0; i < 8; ++i) {
            int idx = tid + i*256;
            int r = idx >> 5, pc = idx & 31;
            int sa = r >> 5, smp = r & 31;
            const char* src = (const char*)g_IFB + (size_t)sa*BB*K1*2
                            + (size_t)(blk*32 + smp)*(K1*2) + pc*16;
            cpa16(sm + Z1_AOFF + r*Z1_ROWB + pc*16, src);
        }
        #pragma unroll
        for (int i = 0; i < 32; ++i) {
            int idx = tid + i*256;
            int r = idx >> 5, pc = idx & 31;
            const char* src = (const char*)g_W1B2 + (size_t)r*(K1*2) + pc*16;
            cpa16(sm + Z1_BOFF + r*Z1_ROWB + pc*16, src);
        }
        #pragma unroll
        for (int i = 0; i < 8; ++i) {      // W2 fp32: 2048 x 16B
            int idx = tid + i*256;
            cpa16(sm + ZW2_OFF + idx*16, (const char*)W2 + idx*16);
        }
        cpa_commit();
    }
    cpa_wait0();
    __syncthreads();
    #pragma unroll 1
    for (int ch = 0; ch < 12; ++ch) {
        int seg = ch >> 2;
        int k0 = (ch & 3) * BK;
        int sa = (seg == 2) ? 1 : 0;
        int sb = (seg == 1) ? 1 : 0;
        const __nv_bfloat16* A = (const __nv_bfloat16*)(sm + Z1_AOFF + sa*32*Z1_ROWB) + k0;
        const __nv_bfloat16* B = (const __nv_bfloat16*)(sm + Z1_BOFF + sb*128*Z1_ROWB) + k0;
        #pragma unroll
        for (int ks = 0; ks < BK/16; ++ks) {
            int k = ks*16 + kb;
            #pragma unroll
            for (int mi = 0; mi < 2; ++mi) {
                int r0 = mi*16 + gr;
                uint32_t a0 = *(const uint32_t*)&A[r0*Z1_ST + k];
                uint32_t a1 = *(const uint32_t*)&A[(r0+8)*Z1_ST + k];
                uint32_t a2 = *(const uint32_t*)&A[r0*Z1_ST + k + 8];
                uint32_t a3 = *(const uint32_t*)&A[(r0+8)*Z1_ST + k + 8];
                #pragma unroll
                for (int ni = 0; ni < 2; ++ni) {
                    int n = w*16 + ni*8 + gr;
                    uint32_t b0 = *(const uint32_t*)&B[n*Z1_ST + k];
                    uint32_t b1v = *(const uint32_t*)&B[n*Z1_ST + k + 8];
                    mma_bf16(d[mi][ni], a0, a1, a2, a3, b0, b1v);
                }
            }
        }
    }
    __syncthreads();   // all MMAs done -> safe to overwrite A region with z1 splits
    {
        float2 bb0 = *(const float2*)&b1[w*16 + (lane & 3)*2];
        float2 bb1 = *(const float2*)&b1[w*16 + 8 + (lane & 3)*2];
        float ps[2][2] = {{0,0},{0,0}}, pq[2][2] = {{0,0},{0,0}};
        #pragma unroll
        for (int mi = 0; mi < 2; ++mi) {
            #pragma unroll
            for (int rr = 0; rr < 2; ++rr) {
                int sl = mi*16 + gr + rr*8;
                #pragma unroll
                for (int ni = 0; ni < 2; ++ni) {
                    int c = w*16 + ni*8 + (lane & 3)*2;
                    float bbx = ni ? bb1.x : bb0.x, bby = ni ? bb1.y : bb0.y;
                    float z0 = d[mi][ni][rr*2]   + bbx; z0 = z0 > 0.f ? z0 : 0.f;
                    float z1v = d[mi][ni][rr*2+1] + bby; z1v = z1v > 0.f ? z1v : 0.f;
                    uint32_t hi, lo;
                    split2(z0, z1v, hi, lo);
                    *(uint32_t*)(sm + Z1_AOFF + sl*Z1_ROWB + c*2)              = hi;
                    *(uint32_t*)(sm + Z1_AOFF + (32 + sl)*Z1_ROWB + c*2)       = lo;
                    ps[ni][0] += z0; ps[ni][1] += z1v;
                    pq[ni][0] += z0*z0; pq[ni][1] += z1v*z1v;
                }
            }
        }
        #pragma unroll
        for (int ni = 0; ni < 2; ++ni) {
            #pragma unroll
            for (int q = 0; q < 2; ++q) {
                #pragma unroll
                for (int o = 4; o <= 16; o <<= 1) {
                    ps[ni][q] += __shfl_xor_sync(0xffffffffu, ps[ni][q], o);
                    pq[ni][q] += __shfl_xor_sync(0xffffffffu, pq[ni][q], o);
                }
            }
            if (lane < 4) {
                int c = w*16 + ni*8 + lane*2;
                atomicAdd(&g_s1[c],   ps[ni][0]); atomicAdd(&g_s1[c+1], ps[ni][1]);
                atomicAdd(&g_q1[c],   pq[ni][0]); atomicAdd(&g_q1[c+1], pq[ni][1]);
            }
        }
    }
    gsync(&g_bar1, 128);

    // ---------------- Phase 2: z2 = relu( z1 @ (W2.*A1)^T + (D1@W2^T + b2) ) -------
    if (tid < DD) {
        float m = __ldcg(&g_s1[tid]) * (1.0f/BB);
        float v = __ldcg(&g_q1[tid]) * (1.0f/BB) - m*m;
        float r = rsqrtf(v + 1e-5f);
        float a = g1[tid] * r;
        A1s[tid] = a;
        D1s[tid] = be1[tid] - m*a;
    }
    __syncthreads();
    {   // fold W2 (from smem fp32) into B region as bf16 splits; compute bconst
        int c = tid >> 2, q = tid & 3;
        const float* wrow = (const float*)(sm + ZW2_OFF) + c*DD + q*32;
        __nv_bfloat16* Bh = (__nv_bfloat16*)(sm + Z1_BOFF + c*Z1_ROWB) + q*32;
        __nv_bfloat16* Bl = (__nv_bfloat16*)(sm + Z1_BOFF + (64 + c)*Z1_ROWB) + q*32;
        float bacc = 0.f;
        #pragma unroll
        for (int j = 0; j < 16; ++j) {
            int k = q*32 + 2*j;
            float w0 = wrow[2*j],  w1 = wrow[2*j+1];
            bacc += D1s[k]*w0 + D1s[k+1]*w1;
            float f0 = w0 * A1s[k], f1 = w1 * A1s[k+1];
            uint32_t hi, lo;
            split2(f0, f1, hi, lo);
            *(uint32_t*)&Bh[2*j] = hi;
            *(uint32_t*)&Bl[2*j] = lo;
        }
        bacc += __shfl_down_sync(0xffffffffu, bacc, 1);
        bacc += __shfl_down_sync(0xffffffffu, bacc, 2);
        if (q == 0) bc[c] = bacc + b2[c];
    }
    __syncthreads();
    float d2[2][4];
    #pragma unroll
    for (int mi = 0; mi < 2; ++mi)
        #pragma unroll
        for (int q = 0; q < 4; ++q) d2[mi][q] = 0.f;
    #pragma unroll 1
    for (int seg = 0; seg < 3; ++seg) {
        int sa = (seg == 2) ? 1 : 0;
        int sb = (seg == 1) ? 1 : 0;
        const __nv_bfloat16* A = (const __nv_bfloat16*)(sm + Z1_AOFF + sa*32*Z1_ROWB);
        const __nv_bfloat16* B = (const __nv_bfloat16*)(sm + Z1_BOFF + sb*64*Z1_ROWB);
        #pragma unroll
        for (int ks = 0; ks < DD/16; ++ks) {
            int k = ks*16 + kb;
            int n = w*8 + gr;
            uint32_t b0 = *(const uint32_t*)&B[n*Z1_ST + k];
            uint32_t b1v = *(const uint32_t*)&B[n*Z1_ST + k + 8];
            #pragma unroll
            for (int mi = 0; mi < 2; ++mi) {
                int r0 = mi*16 + gr;
                uint32_t a0 = *(const uint32_t*)&A[r0*Z1_ST + k];
                uint32_t a1 = *(const uint32_t*)&A[(r0+8)*Z1_ST + k];
                uint32_t a2 = *(const uint32_t*)&A[r0*Z1_ST + k + 8];
                uint32_t a3 = *(const uint32_t*)&A[(r0+8)*Z1_ST + k + 8];
                mma_bf16(d2[mi], a0, a1, a2, a3, b0, b1v);
            }
        }
    }
    {
        int c0 = w*8 + (lane & 3)*2;
        float2 bcv = *(const float2*)&bc[c0];
        float ps0 = 0.f, ps1 = 0.f, pq0 = 0.f, pq1 = 0.f;
        #pragma unroll
        for (int mi = 0; mi < 2; ++mi) {
            #pragma unroll
            for (int rr = 0; rr < 2; ++rr) {
                int sl = mi*16 + gr + rr*8;
                float z0 = d2[mi][rr*2]   + bcv.x; z0 = z0 > 0.f ? z0 : 0.f;
                float z1v = d2[mi][rr*2+1] + bcv.y; z1v = z1v > 0.f ? z1v : 0.f;
                z2s[sl][c0] = z0;  z2s[sl][c0+1] = z1v;
                ps0 += z0; ps1 += z1v; pq0 += z0*z0; pq1 += z1v*z1v;
            }
        }
        #pragma unroll
        for (int o = 4; o <= 16; o <<= 1) {
            ps0 += __shfl_xor_sync(0xffffffffu, ps0, o);
            ps1 += __shfl_xor_sync(0xffffffffu, ps1, o);
            pq0 += __shfl_xor_sync(0xffffffffu, pq0, o);
            pq1 += __shfl_xor_sync(0xffffffffu, pq1, o);
        }
        if (lane < 4) {
            atomicAdd(&g_s2[c0],   ps0); atomicAdd(&g_s2[c0+1], ps1);
            atomicAdd(&g_q2[c0],   pq0); atomicAdd(&g_q2[c0+1], pq1);
        }
    }
    gsync(&g_bar2, 128);

    // ---------------- Phase 3: pred = sigmoid(BN(z2) @ Wp^T + bp) ------------------
    if (tid < D2) {
        float m = __ldcg(&g_s2[tid]) * (1.0f/BB);
        float v = __ldcg(&g_q2[tid]) * (1.0f/BB) - m*m;
        float r = rsqrtf(v + 1e-5f);
        float a = g2[tid] * r;
        A2s[tid] = a;
        D2s[tid] = be2[tid] - m*a;
    }
    __syncthreads();
    {
        int c = lane*2;
        float2 wp = *(const float2*)&Wp[c];
        float a0 = A2s[c], a1 = A2s[c+1], dd0 = D2s[c], dd1 = D2s[c+1];
        float bpv = bp[0];
        #pragma unroll
        for (int i = 0; i < 4; ++i) {
            int sl = w*4 + i;
            float t = (z2s[sl][c]*a0 + dd0)*wp.x + (z2s[sl][c+1]*a1 + dd1)*wp.y;
            #pragma unroll
            for (int o = 16; o; o >>= 1) t += __shfl_down_sync(0xffffffffu, t, o);
            if (lane == 0)
                out_pred[blk*32 + sl] = 1.0f / (1.0f + expf(-(t + bpv)));
        }
    }
}

// ---------------- launch ------------------------------------------------------------
extern "C" void kernel_launch(void* const* d_in, const int* in_sizes, int n_in,
                              void* d_out, int out_size) {
    const int*   nodes_u     = (const int*)  d_in[0];
    const int*   nodes_v     = (const int*)  d_in[1];
    const int*   nodes_d     = (const int*)  d_in[2];
    const int*   inter_items = (const int*)  d_in[3];
    const int*   top_n       = (const int*)  d_in[4];
    const float* protos      = (const float*)d_in[5];
    const float* pre_text    = (const float*)d_in[6];
    const float* pre_visual  = (const float*)d_in[7];
    const float* Wt          = (const float*)d_in[8];
    const float* bt          = (const float*)d_in[9];
    const float* Wv          = (const float*)d_in[10];
    const float* bv          = (const float*)d_in[11];
    const float* up          = (const float*)d_in[12];
    const float* ip          = (const float*)d_in[13];
    const float* dp          = (const float*)d_in[14];
    const float* W1          = (const float*)d_in[15];
    const float* b1          = (const float*)d_in[16];
    const float* g1          = (const float*)d_in[17];
    const float* be1         = (const float*)d_in[18];
    const float* W2          = (const float*)d_in[19];
    const float* b2          = (const float*)d_in[20];
    const float* g2          = (const float*)d_in[21];
    const float* be2         = (const float*)d_in[22];
    const float* Wp          = (const float*)d_in[23];
    const float* bp          = (const float*)d_in[24];

    float* out      = (float*)d_out;
    float* out_pred = out;
    float* out_pu   = out + BB;
    float* out_hu   = out + BB + BB*DD;
    float* out_pd   = out + BB + 2*BB*DD;

    cudaFuncSetAttribute(k_eh,   cudaFuncAttributeMaxDynamicSharedMemorySize, EH_SMEM);
    cudaFuncSetAttribute(k_tail, cudaFuncAttributeMaxDynamicSharedMemorySize, ZT_SMEM);

    k_prep<<<328, 128>>>(Wt, Wv, W1, protos, bt, bv);
    k_eh<<<256, 256, EH_SMEM>>>(nodes_v, pre_text, pre_visual, ip,
                                nodes_u, nodes_d, inter_items, top_n,
                                up, dp, out_pu, out_pd, out_hu);
    k_tail<<<128, 256, ZT_SMEM>>>(b1, b2, g1, be1, W2, g2, be2, Wp, bp, out_pred);
}